// round 15
// baseline (speedup 1.0000x reference)
#include <cuda_runtime.h>
#include <cuda_bf16.h>
#include <math.h>

// ---------------------------------------------------------------------------
// PhysicsAwareMSELoss — ONE fused kernel, grid = B blocks, WARP-SPECIALIZED.
//   Block b (256 threads):
//     warps 0-3 : stats for sample b. 16 elems/thread (12x LDG.128, 1 DRAM
//                 round). Warp shuffle reduce; named barrier bar.sync(1,128)
//                 (stats warps only); thread 0 finishes per-sample math and
//                 red-adds 4 scaled-int64 partials.
//     warps 4-7 : pairs (b, j) for all j, CONCURRENT with stats warps.
//                 Per-thread __ldg scalar screen (no smem, no barriers);
//                 ballot-walk survivors in lane order; warp-reduce D over S
//                 (row b L2-hot: stats warps stream it simultaneously);
//                 lane 0 red-adds 4 scaled-int64 partials.
//   sync: one __syncthreads at the end; thread 0: atom.add.acq_rel.gpu
//         ticket. Last block's thread 0 reads 8 summed accumulators,
//         writes out[0], resets state.
//   Determinism: int64 adds commute exactly; survivor walk is lane-ordered.
// ---------------------------------------------------------------------------

#define ALPHA  0.7f
#define BETA   0.3f

// fixed-point scale 2^34: quantization ~6e-11 abs/term, sums << 2^63
#define SC_F   1.7179869184e10f
#define SC_INV 5.8207660913467407e-11

// acc: 0:wmse 1:el_err 2:el_valid 3:mono 4:tsum 5:tcnt 6:ssum 7:scnt
__device__ unsigned long long g_acc[8];   // zero-init; reset by last block
__device__ unsigned int g_ticket;          // zero-init; reset by last block

__device__ __forceinline__ float reluf(float x) { return fmaxf(x, 0.f); }

__device__ __forceinline__ void acc_add(int k, float v)
{
    atomicAdd(&g_acc[k], (unsigned long long)llrintf(v * SC_F));
}

__device__ __forceinline__ unsigned int ticket_add_acq_rel(unsigned int* p)
{
    unsigned int old;
    asm volatile("atom.add.acq_rel.gpu.u32 %0, [%1], 1;"
                 : "=r"(old) : "l"(p) : "memory");
    return old;
}

__device__ __forceinline__ void pair_masks(int mi, int mj,
                                           float sri, float srj,
                                           float ti, float tj,
                                           bool& tmask_ij, bool& smask_ij)
{
    bool same   = (mi == mj);
    float hi    = fmaxf(sri, srj);
    float lo    = fminf(sri, srj);
    float ratio = hi / (lo + 1e-8f);
    float tdiff = ti - tj;
    tmask_ij = same && (ratio <= 1.2f) && (fabsf(tdiff) >= 10.f) && (tdiff > 0.f);
    smask_ij = same && (fabsf(tdiff) <= 10.f) && (ratio >= 1.2f) && (sri > srj);
}

__global__ void __launch_bounds__(256)
fused_kernel(const float* __restrict__ pred,
             const float* __restrict__ target,
             const int*   __restrict__ mat,
             const float* __restrict__ strain,
             const float* __restrict__ E,
             const float* __restrict__ temp,
             const float* __restrict__ sr,
             const float* __restrict__ w,
             float* __restrict__ out,
             int B, int S, int nW)
{
    const int tid  = threadIdx.x;
    const int lane = tid & 31;
    const int wid  = tid >> 5;
    const int b    = blockIdx.x;
    const unsigned FULL = 0xFFFFFFFFu;

    __shared__ float sh[7][4];

    if (wid < 4) {
        // ================= stats warps (threads 0-127): sample b =================
        // scalar prefetch under the row-load shadow (warp 0 lanes)
        float wl = 0.f; int mbl = 0; float Ebl = 0.f;
        if (wid == 0) {
            if (lane < nW) wl = w[lane];
            if (lane == 0) { mbl = mat[b]; Ebl = E[b]; }
        }

        const float* p = pred   + (size_t)b * S;
        const float* t = target + (size_t)b * S;
        const float* e = strain + (size_t)b * S;

        float v[7];   // d2, cnt, sx, sy, sxy, sxx, mono
        #pragma unroll
        for (int k = 0; k < 7; k++) v[k] = 0.f;

        for (int base = 0; base < S; base += 2048) {
            const int e0 = base + tid * 16;
            if (e0 + 15 < S) {
                float pv[16], tv[16], ev[16];
                #pragma unroll
                for (int c = 0; c < 4; c++) {
                    float4 pq = *reinterpret_cast<const float4*>(p + e0 + 4*c);
                    float4 tq = *reinterpret_cast<const float4*>(t + e0 + 4*c);
                    float4 eq = *reinterpret_cast<const float4*>(e + e0 + 4*c);
                    pv[4*c+0]=pq.x; pv[4*c+1]=pq.y; pv[4*c+2]=pq.z; pv[4*c+3]=pq.w;
                    tv[4*c+0]=tq.x; tv[4*c+1]=tq.y; tv[4*c+2]=tq.z; tv[4*c+3]=tq.w;
                    ev[4*c+0]=eq.x; ev[4*c+1]=eq.y; ev[4*c+2]=eq.z; ev[4*c+3]=eq.w;
                }

                #pragma unroll
                for (int q = 0; q < 16; q++) {
                    float d = pv[q] - tv[q];
                    v[0] += d * d;
                    if (ev[q] < 0.02f) {
                        v[1] += 1.f; v[2] += ev[q]; v[3] += pv[q];
                        v[4] += ev[q] * pv[q]; v[5] += ev[q] * ev[q];
                    }
                }
                #pragma unroll
                for (int q = 0; q < 15; q++)
                    v[6] += reluf(pv[q] - pv[q + 1]);
                float nxt = __shfl_down_sync(FULL, pv[0], 1);
                if (lane == 31) nxt = (e0 + 16 < S) ? p[e0 + 16] : pv[15]; // => relu 0
                v[6] += reluf(pv[15] - nxt);
            } else if (e0 < S) {
                for (int i = e0; i < S && i < e0 + 16; i++) {
                    float pvv = p[i], tvv = t[i], evv = e[i];
                    float d = pvv - tvv; v[0] += d * d;
                    if (evv < 0.02f) { v[1] += 1.f; v[2] += evv; v[3] += pvv;
                                       v[4] += evv*pvv; v[5] += evv*evv; }
                    if (i < S - 1) v[6] += reluf(pvv - p[i + 1]);
                }
            }
        }

        #pragma unroll
        for (int k = 0; k < 7; k++) {
            #pragma unroll
            for (int off = 16; off > 0; off >>= 1)
                v[k] += __shfl_xor_sync(FULL, v[k], off);
        }
        if (lane == 0) {
            #pragma unroll
            for (int k = 0; k < 7; k++) sh[k][wid] = v[k];
        }

        // register-only scalar select in warp 0
        float wsel = 0.f, Eb = 0.f;
        if (wid == 0) {
            const int mb = __shfl_sync(FULL, mbl, 0);
            Eb   = __shfl_sync(FULL, Ebl, 0);
            wsel = __shfl_sync(FULL, wl, mb & 31);
        }

        // named barrier: ONLY the 4 stats warps (pair warps run free)
        asm volatile("bar.sync 1, 128;" ::: "memory");

        if (tid == 0) {
            float r[7];
            #pragma unroll
            for (int k = 0; k < 7; k++)
                r[k] = sh[k][0] + sh[k][1] + sh[k][2] + sh[k][3];

            float wmse = (r[0] / (float)S) * wsel;
            float cnt = r[1], Sx = r[2], Sy = r[3], Sxy = r[4], Sxx = r[5];
            float el_err = 0.f, el_valid = 0.f;
            if (cnt >= 2.f) {
                float safe  = fmaxf(cnt, 1.f);
                float eps_m = Sx / safe;
                float sig_m = Sy / safe;
                float cov = Sxy - sig_m * Sx - eps_m * Sy + cnt * eps_m * sig_m;
                float var = Sxx - 2.f * eps_m * Sx + cnt * eps_m * eps_m;
                float et  = Eb * 1000.f;
                el_err   = fabsf(cov / (var + 1e-8f) - et) / (et + 1e-8f);
                el_valid = 1.f;
            }
            acc_add(0, wmse);
            acc_add(1, el_err);
            acc_add(2, el_valid);
            acc_add(3, r[6]);
        }
    } else {
        // ================= pair warps (threads 128-255): pairs (b, j) ============
        // uniform b-scalars (L2 broadcast) + per-thread j-scalars: 1 load round
        const int   mb_ = __ldg(mat + b);
        const float srb = __ldg(sr + b);
        const float tb  = __ldg(temp + b);

        float tsum = 0.f, tcnt = 0.f, ssum = 0.f, scnt = 0.f;
        const int S4 = S >> 2;
        const int nRounds = (B + 127) / 128;

        for (int r = 0; r < nRounds; r++) {
            const int j = r * 128 + (tid - 128);
            bool t_bj = false, s_jb = false;
            int  jv = 0;
            if (j < B && j != b) {
                jv = j;
                const int   mj  = __ldg(mat + j);
                const float srj = __ldg(sr + j);
                const float tj  = __ldg(temp + j);
                bool sd, td;
                pair_masks(mb_, mj, srb, srj, tb, tj, t_bj, sd);
                pair_masks(mj, mb_, srj, srb, tj, tb, td, s_jb);
            }
            const bool need = t_bj || s_jb;

            unsigned bal = __ballot_sync(FULL, need);
            while (bal) {
                const int src = __ffs(bal) - 1;
                bal &= bal - 1;
                const int jj = __shfl_sync(FULL, jv, src);
                const int tt = __shfl_sync(FULL, (int)t_bj, src);
                const int ss = __shfl_sync(FULL, (int)s_jb, src);

                const float4* si = reinterpret_cast<const float4*>(pred + (size_t)b  * S);
                const float4* sj = reinterpret_cast<const float4*>(pred + (size_t)jj * S);
                float acc = 0.f;
                #pragma unroll 8
                for (int k = lane; k < S4; k += 32) {
                    float4 a = si[k], bq = sj[k];
                    acc += reluf(a.x - bq.x) + reluf(a.y - bq.y)
                         + reluf(a.z - bq.z) + reluf(a.w - bq.w);
                }
                // scalar tail (S not multiple of 4) — contributes identically on all lanes
                if (S & 3) {
                    if (lane == 0) {
                        const float* pb = pred + (size_t)b  * S;
                        const float* pj = pred + (size_t)jj * S;
                        for (int k = S & ~3; k < S; k++)
                            acc += reluf(pb[k] - pj[k]);
                    }
                }
                #pragma unroll
                for (int off = 16; off > 0; off >>= 1)
                    acc += __shfl_xor_sync(FULL, acc, off);
                const float D = acc / (float)S;       // uniform across lanes
                if (tt) { tsum += D; tcnt += 1.f; }
                if (ss) { ssum += D; scnt += 1.f; }
            }
        }

        if (lane == 0 && (tcnt > 0.f || scnt > 0.f)) {
            acc_add(4, tsum);
            acc_add(5, tcnt);
            acc_add(6, ssum);
            acc_add(7, scnt);
        }
    }

    // ====== end: one block barrier, ticket, single-thread epilogue ======
    __syncthreads();
    if (tid == 0) {
        const unsigned int vtk = ticket_add_acq_rel(&g_ticket);
        if (vtk == gridDim.x - 1) {
            double a0 = (double)__ldcg(&g_acc[0]) * SC_INV;
            double a1 = (double)__ldcg(&g_acc[1]) * SC_INV;
            double a2 = (double)__ldcg(&g_acc[2]) * SC_INV;
            double a3 = (double)__ldcg(&g_acc[3]) * SC_INV;
            double a4 = (double)__ldcg(&g_acc[4]) * SC_INV;
            double a5 = (double)__ldcg(&g_acc[5]) * SC_INV;
            double a6 = (double)__ldcg(&g_acc[6]) * SC_INV;
            double a7 = (double)__ldcg(&g_acc[7]) * SC_INV;

            float mse_loss  = (float)a0 / (float)B;
            float elastic   = (a2 > 0.5) ? (float)a1 / fmaxf((float)a2, 1.f) : 0.f;
            float mono      = (float)a3 / (float)(B * (S - 1));
            float temp_loss = (a5 > 0.5) ? (float)a4 / fmaxf((float)a5, 1.f) : 0.f;
            float sr_loss   = (a7 > 0.5) ? (float)a6 / fmaxf((float)a7, 1.f) : 0.f;
            out[0] = ALPHA * mse_loss + BETA * (elastic + mono + temp_loss + sr_loss);

            #pragma unroll
            for (int k = 0; k < 8; k++) g_acc[k] = 0ull;
            g_ticket = 0;
        }
    }
}

// --------------------------------------------------------------------------
extern "C" void kernel_launch(void* const* d_in, const int* in_sizes, int n_in,
                              void* d_out, int out_size)
{
    const float* pred   = (const float*)d_in[0];
    const float* target = (const float*)d_in[1];
    const int*   matid  = (const int*)  d_in[2];
    const float* strain = (const float*)d_in[3];
    const float* E_GPa  = (const float*)d_in[4];
    const float* temp   = (const float*)d_in[5];
    const float* sr     = (const float*)d_in[6];
    const float* mw     = (const float*)d_in[7];
    float* out = (float*)d_out;

    const int B  = in_sizes[2];         // material_ids count
    const int S  = in_sizes[0] / B;     // pred = B*S
    const int nW = in_sizes[7];         // material_weights count

    fused_kernel<<<B, 256>>>(pred, target, matid, strain, E_GPa, temp, sr, mw,
                             out, B, S, nW);
}

// round 16
// speedup vs baseline: 1.1633x; 1.1633x over previous
#include <cuda_runtime.h>
#include <cuda_bf16.h>
#include <math.h>

// ---------------------------------------------------------------------------
// PhysicsAwareMSELoss — ONE fused kernel, scoped-atomic sync.  (FINAL: best
// measured variant, round 9, 10.75us.)
//   sample blocks (B): 256 threads x 8 elems; block reduces 7 sums; thread 0
//                      finishes per-sample math -> g_samp[4][b].
//   strip blocks (64): 256 threads screen 256 fixed pairs (smem scalars);
//                      survivors compacted block-wide via ballot+prefix
//                      (deterministic, no atomics), dealt round-robin to the
//                      8 warps; per pair: lane-strided loop with unroll 8
//                      (MLP 16) -> g_pairAcc[4][strip].
//   sync: thread 0 per block: atom.add.acq_rel.gpu (no MEMBAR anywhere).
//         Last block sums 768 floats via __ldcg, writes out[0], resets ticket.
// ---------------------------------------------------------------------------

#define MAXB    256
#define MAXSTRP 256
#define ALPHA   0.7f
#define BETA    0.3f
#define STRIP   256     // pairs screened per strip block

__device__ float g_samp[4][MAXB];        // 0:wmse 1:el_err 2:el_valid 3:mono
__device__ float g_pairAcc[4][MAXSTRP];  // 0:tsum 1:tcnt 2:ssum 3:scnt
__device__ unsigned int g_ticket;        // zero-init; reset by last block

__device__ __forceinline__ float reluf(float x) { return fmaxf(x, 0.f); }

__device__ __forceinline__ unsigned int ticket_add_acq_rel(unsigned int* p)
{
    unsigned int old;
    asm volatile("atom.add.acq_rel.gpu.u32 %0, [%1], 1;"
                 : "=r"(old) : "l"(p) : "memory");
    return old;
}

__device__ __forceinline__ void pair_masks(int mi, int mj,
                                           float sri, float srj,
                                           float ti, float tj,
                                           bool& tmask_ij, bool& smask_ij)
{
    bool same   = (mi == mj);
    float hi    = fmaxf(sri, srj);
    float lo    = fminf(sri, srj);
    float ratio = hi / (lo + 1e-8f);
    float tdiff = ti - tj;
    tmask_ij = same && (ratio <= 1.2f) && (fabsf(tdiff) >= 10.f) && (tdiff > 0.f);
    smask_ij = same && (fabsf(tdiff) <= 10.f) && (ratio >= 1.2f) && (sri > srj);
}

__global__ void __launch_bounds__(256)
fused_kernel(const float* __restrict__ pred,
             const float* __restrict__ target,
             const int*   __restrict__ mat,
             const float* __restrict__ strain,
             const float* __restrict__ E,
             const float* __restrict__ temp,
             const float* __restrict__ sr,
             const float* __restrict__ w,
             float* __restrict__ out,
             int B, int S, int nStrips)
{
    const int tid  = threadIdx.x;
    const int lane = tid & 31;
    const int wid  = tid >> 5;

    __shared__ float sh[8][8];
    __shared__ bool  sh_last;

    if (blockIdx.x < (unsigned)B) {
        // ---------------- one block per sample: stats + per-sample math ----------
        const int b = blockIdx.x;
        const float* p = pred   + (size_t)b * S;
        const float* t = target + (size_t)b * S;
        const float* e = strain + (size_t)b * S;

        float v[7];   // d2, cnt, sx, sy, sxy, sxx, mono
        #pragma unroll
        for (int k = 0; k < 7; k++) v[k] = 0.f;

        for (int base = 0; base < S; base += 2048) {
            const int e0 = base + tid * 8;
            if (e0 + 7 < S) {
                float4 p0 = *reinterpret_cast<const float4*>(p + e0);
                float4 p1 = *reinterpret_cast<const float4*>(p + e0 + 4);
                float4 t0 = *reinterpret_cast<const float4*>(t + e0);
                float4 t1 = *reinterpret_cast<const float4*>(t + e0 + 4);
                float4 ea = *reinterpret_cast<const float4*>(e + e0);
                float4 eb = *reinterpret_cast<const float4*>(e + e0 + 4);

                float pv[8] = {p0.x,p0.y,p0.z,p0.w,p1.x,p1.y,p1.z,p1.w};
                float tv[8] = {t0.x,t0.y,t0.z,t0.w,t1.x,t1.y,t1.z,t1.w};
                float ev[8] = {ea.x,ea.y,ea.z,ea.w,eb.x,eb.y,eb.z,eb.w};

                #pragma unroll
                for (int q = 0; q < 8; q++) {
                    float d = pv[q] - tv[q];
                    v[0] += d * d;
                    if (ev[q] < 0.02f) {
                        v[1] += 1.f; v[2] += ev[q]; v[3] += pv[q];
                        v[4] += ev[q] * pv[q]; v[5] += ev[q] * ev[q];
                    }
                }
                #pragma unroll
                for (int q = 0; q < 7; q++)
                    v[6] += reluf(pv[q] - pv[q + 1]);
                float nxt = __shfl_down_sync(0xFFFFFFFFu, pv[0], 1);
                if (lane == 31) nxt = (e0 + 8 < S) ? p[e0 + 8] : pv[7]; // => relu 0
                v[6] += reluf(pv[7] - nxt);
            } else if (e0 < S) {
                for (int i = e0; i < S && i < e0 + 8; i++) {
                    float pvv = p[i], tvv = t[i], evv = e[i];
                    float d = pvv - tvv; v[0] += d * d;
                    if (evv < 0.02f) { v[1] += 1.f; v[2] += evv; v[3] += pvv;
                                       v[4] += evv*pvv; v[5] += evv*evv; }
                    if (i < S - 1) v[6] += reluf(pvv - p[i + 1]);
                }
            }
        }

        #pragma unroll
        for (int k = 0; k < 7; k++) {
            #pragma unroll
            for (int off = 16; off > 0; off >>= 1)
                v[k] += __shfl_xor_sync(0xFFFFFFFFu, v[k], off);
        }
        if (lane == 0) {
            #pragma unroll
            for (int k = 0; k < 7; k++) sh[k][wid] = v[k];
        }
        __syncthreads();
        if (tid == 0) {
            float r[7];
            #pragma unroll
            for (int k = 0; k < 7; k++) {
                r[k] = 0.f;
                #pragma unroll
                for (int q = 0; q < 8; q++) r[k] += sh[k][q];
            }
            float wmse = (r[0] / (float)S) * w[mat[b]];
            float cnt = r[1], Sx = r[2], Sy = r[3], Sxy = r[4], Sxx = r[5];
            float el_err = 0.f, el_valid = 0.f;
            if (cnt >= 2.f) {
                float safe  = fmaxf(cnt, 1.f);
                float eps_m = Sx / safe;
                float sig_m = Sy / safe;
                float cov = Sxy - sig_m * Sx - eps_m * Sy + cnt * eps_m * sig_m;
                float var = Sxx - 2.f * eps_m * Sx + cnt * eps_m * eps_m;
                float et  = E[b] * 1000.f;
                el_err   = fabsf(cov / (var + 1e-8f) - et) / (et + 1e-8f);
                el_valid = 1.f;
            }
            g_samp[0][b] = wmse;
            g_samp[1][b] = el_err;
            g_samp[2][b] = el_valid;
            g_samp[3][b] = r[6];
        }
    } else {
        // ------- strip block: screen, deterministic compaction, balanced reduce -------
        __shared__ int   s_mat[MAXB];
        __shared__ float s_sr[MAXB];
        __shared__ float s_temp[MAXB];
        __shared__ int   s_list[STRIP];   // packed: (local_tid<<2)|(t_ij<<1)|s_ji
        __shared__ int   s_wcnt[8];
        __shared__ int   s_wbase[8];
        __shared__ int   s_total;

        const int strip = blockIdx.x - B;
        const int totalPairs = B * B;

        for (int b = tid; b < B; b += 256) {
            s_mat[b]  = mat[b];
            s_sr[b]   = sr[b];
            s_temp[b] = temp[b];
        }
        __syncthreads();

        // each thread screens exactly one fixed pair
        const int idx = strip * STRIP + tid;
        bool t_ij = false, s_ji = false;
        if (idx < totalPairs) {
            const int i = idx / B;
            const int j = idx - i * B;
            bool sd, td;
            pair_masks(s_mat[i], s_mat[j], s_sr[i], s_sr[j],
                       s_temp[i], s_temp[j], t_ij, sd);
            pair_masks(s_mat[j], s_mat[i], s_sr[j], s_sr[i],
                       s_temp[j], s_temp[i], td, s_ji);
        }
        const bool need = t_ij || s_ji;

        // deterministic block-wide compaction: ballot + per-warp prefix
        const unsigned bal  = __ballot_sync(0xFFFFFFFFu, need);
        const int      rank = __popc(bal & ((1u << lane) - 1u));
        if (lane == 0) s_wcnt[wid] = __popc(bal);
        __syncthreads();
        if (tid == 0) {
            int run = 0;
            #pragma unroll
            for (int q = 0; q < 8; q++) { s_wbase[q] = run; run += s_wcnt[q]; }
            s_total = run;
        }
        __syncthreads();
        if (need)
            s_list[s_wbase[wid] + rank] = (tid << 2) | ((int)t_ij << 1) | (int)s_ji;
        __syncthreads();

        // deal survivors round-robin to warps; high-MLP per-pair reduce
        const int total = s_total;
        float tsum = 0.f, tcnt = 0.f, ssum = 0.f, scnt = 0.f;
        const int S4 = S >> 2;
        for (int li = wid; li < total; li += 8) {
            const int packed = s_list[li];
            const int pidx   = strip * STRIP + (packed >> 2);
            const int tt     = (packed >> 1) & 1;
            const int ss     = packed & 1;
            const int i = pidx / B;
            const int j = pidx - i * B;

            const float4* si = reinterpret_cast<const float4*>(pred + (size_t)i * S);
            const float4* sj = reinterpret_cast<const float4*>(pred + (size_t)j * S);
            float acc = 0.f;
            #pragma unroll 8
            for (int k = lane; k < S4; k += 32) {
                float4 a = si[k], bq = sj[k];
                acc += reluf(a.x - bq.x) + reluf(a.y - bq.y)
                     + reluf(a.z - bq.z) + reluf(a.w - bq.w);
            }
            #pragma unroll
            for (int off = 16; off > 0; off >>= 1)
                acc += __shfl_xor_sync(0xFFFFFFFFu, acc, off);
            const float D = acc / (float)S;
            if (tt) { tsum += D; tcnt += 1.f; }
            if (ss) { ssum += D; scnt += 1.f; }
        }

        if (lane == 0) {
            sh[0][wid] = tsum; sh[1][wid] = tcnt;
            sh[2][wid] = ssum; sh[3][wid] = scnt;
        }
        __syncthreads();
        if (tid == 0) {
            float r0 = 0.f, r1 = 0.f, r2 = 0.f, r3 = 0.f;
            #pragma unroll
            for (int q = 0; q < 8; q++) {
                r0 += sh[0][q]; r1 += sh[1][q];
                r2 += sh[2][q]; r3 += sh[3][q];
            }
            g_pairAcc[0][strip] = r0;
            g_pairAcc[1][strip] = r1;
            g_pairAcc[2][strip] = r2;
            g_pairAcc[3][strip] = r3;
        }
    }

    // ============ sync: scoped atomic only (no MEMBAR anywhere) ============
    if (tid == 0) {
        unsigned int v = ticket_add_acq_rel(&g_ticket);
        sh_last = (v == gridDim.x - 1);
    }
    __syncthreads();
    if (!sh_last) return;

    // ---- last block: sum 4*B + 4*nStrips floats (L2-direct), write scalar ----
    float acc8[8];
    #pragma unroll
    for (int k = 0; k < 8; k++) acc8[k] = 0.f;

    for (int b = tid; b < B; b += 256) {
        acc8[0] += __ldcg(&g_samp[0][b]);
        acc8[1] += __ldcg(&g_samp[1][b]);
        acc8[2] += __ldcg(&g_samp[2][b]);
        acc8[3] += __ldcg(&g_samp[3][b]);
    }
    for (int s = tid; s < nStrips; s += 256) {
        acc8[4] += __ldcg(&g_pairAcc[0][s]);
        acc8[5] += __ldcg(&g_pairAcc[1][s]);
        acc8[6] += __ldcg(&g_pairAcc[2][s]);
        acc8[7] += __ldcg(&g_pairAcc[3][s]);
    }

    #pragma unroll
    for (int k = 0; k < 8; k++) {
        #pragma unroll
        for (int off = 16; off > 0; off >>= 1)
            acc8[k] += __shfl_xor_sync(0xFFFFFFFFu, acc8[k], off);
    }
    __syncthreads();                 // sh[][] reuse
    if (lane == 0) {
        #pragma unroll
        for (int k = 0; k < 8; k++) sh[k][wid] = acc8[k];
    }
    __syncthreads();
    if (tid == 0) {
        float r[8];
        #pragma unroll
        for (int k = 0; k < 8; k++) {
            r[k] = 0.f;
            #pragma unroll
            for (int q = 0; q < 8; q++) r[k] += sh[k][q];
        }
        float mse_loss  = r[0] / (float)B;
        float elastic   = (r[2] > 0.f) ? r[1] / fmaxf(r[2], 1.f) : 0.f;
        float mono      = r[3] / (float)(B * (S - 1));
        float temp_loss = (r[5] > 0.f) ? r[4] / fmaxf(r[5], 1.f) : 0.f;
        float sr_loss   = (r[7] > 0.f) ? r[6] / fmaxf(r[7], 1.f) : 0.f;
        out[0] = ALPHA * mse_loss + BETA * (elastic + mono + temp_loss + sr_loss);
        g_ticket = 0;   // reset for next graph replay
    }
}

// --------------------------------------------------------------------------
extern "C" void kernel_launch(void* const* d_in, const int* in_sizes, int n_in,
                              void* d_out, int out_size)
{
    const float* pred   = (const float*)d_in[0];
    const float* target = (const float*)d_in[1];
    const int*   matid  = (const int*)  d_in[2];
    const float* strain = (const float*)d_in[3];
    const float* E_GPa  = (const float*)d_in[4];
    const float* temp   = (const float*)d_in[5];
    const float* sr     = (const float*)d_in[6];
    const float* mw     = (const float*)d_in[7];
    float* out = (float*)d_out;

    const int B = in_sizes[2];          // material_ids count
    const int S = in_sizes[0] / B;      // pred = B*S

    const int pairStrips = (B * B + STRIP - 1) / STRIP;   // 64 for B=128
    const int grid       = B + pairStrips;                 // 192 blocks

    fused_kernel<<<grid, 256>>>(pred, target, matid, strain, E_GPa, temp, sr, mw,
                                out, B, S, pairStrips);
}